// round 12
// baseline (speedup 1.0000x reference)
#include <cuda_runtime.h>
#include <cuda_fp16.h>
#include <cstdint>

// Problem constants
#define CD    1024   // d_model
#define TQN   1024   // query tokens
#define NH    16     // heads
#define HD    64     // head dim
#define NKEY  512    // keys per head after HEPOS gather (8192/16)

#define AST   72     // smem row stride in halves (64 + 8 pad; 36 words -> conflict-free)

// ---------------------------------------------------------------------------
// Scratch (device globals; runtime allocation is forbidden)
// ---------------------------------------------------------------------------
__device__ __align__(256) float g_Qp[TQN * CD];          // Q projection
__device__ __align__(256) float g_Kg[NH * NKEY * HD];    // gathered/projected K [h][j][d]
__device__ __align__(256) float g_Vg[NH * NKEY * HD];    // gathered/projected V [h][j][d]
__device__ __align__(256) float g_AO[TQN * CD];          // attention output

// ---------------------------------------------------------------------------
// fp16 mma.sync helpers (legacy tensor-core path, base sm_100 target)
// ---------------------------------------------------------------------------
// pack2(lo, hi): f16x2 with lower half = lo  (cvt.rn.f16x2.f32 d,a,b: d.hi=a, d.lo=b)
__device__ __forceinline__ uint32_t pack2(float lo, float hi) {
    uint32_t r;
    asm("cvt.rn.f16x2.f32 %0, %1, %2;" : "=r"(r) : "f"(hi), "f"(lo));
    return r;
}
// D(16x8,f32) += A(16x16,f16) * B(16x8,f16)
__device__ __forceinline__ void mma16(float* c, const uint32_t* a, const uint32_t* b) {
    asm volatile(
        "mma.sync.aligned.m16n8k16.row.col.f32.f16.f16.f32 "
        "{%0,%1,%2,%3}, {%4,%5,%6,%7}, {%8,%9}, {%0,%1,%2,%3};\n"
        : "+f"(c[0]), "+f"(c[1]), "+f"(c[2]), "+f"(c[3])
        : "r"(a[0]), "r"(a[1]), "r"(a[2]), "r"(a[3]), "r"(b[0]), "r"(b[1]));
}

// ---------------------------------------------------------------------------
// Shared GEMM core (fp16 mma): C[cm0+m, cn0+n] = sum_k A[(m0+m)*rowMul, k] *
// B[n, k] + bias[n].  BM=128, BN=64, BK=64, 256 threads = 8 warps (4M x 2N),
// warp tile 32x32, register-prefetch software pipeline.  Prefetch is packed
// to f16x2 at LDG time (uint2, 24 regs vs 48 for raw float4) so the kernel
// fits 2 CTAs/SM under __launch_bounds__(256,2).
// ---------------------------------------------------------------------------
__device__ __forceinline__ void gemm_core(
    const float* __restrict__ Ab, int lda, int rowMul, int m0,
    const float* __restrict__ Bb, int ldb,
    const float* __restrict__ biasb,
    float* __restrict__ Cb, int ldc, int cm0, int cn0, int K,
    uint16_t* As2, uint16_t* Bs2)
{
    const int tid  = threadIdx.x;
    const int wid  = tid >> 5;
    const int lane = tid & 31;
    const int g    = lane >> 2;
    const int tc   = lane & 3;
    const int wm   = wid & 3;
    const int wn   = wid >> 2;

    uint2 areg[8], breg[4];
    auto ldg_chunk = [&](int k0) {
        #pragma unroll
        for (int it = 0; it < 8; it++) {
            int i = tid + it * 256;
            int r = i >> 4, cc = (i & 15) << 2;
            float4 t = *(const float4*)(Ab + (long)(m0 + r) * rowMul * lda + k0 + cc);
            areg[it].x = pack2(t.x, t.y);
            areg[it].y = pack2(t.z, t.w);
        }
        #pragma unroll
        for (int it = 0; it < 4; it++) {
            int i = tid + it * 256;
            int r = i >> 4, cc = (i & 15) << 2;
            float4 t = *(const float4*)(Bb + (long)r * ldb + k0 + cc);
            breg[it].x = pack2(t.x, t.y);
            breg[it].y = pack2(t.z, t.w);
        }
    };
    auto sts_chunk = [&]() {
        #pragma unroll
        for (int it = 0; it < 8; it++) {
            int i = tid + it * 256;
            int r = i >> 4, cc = (i & 15) << 2;
            *(uint2*)&As2[r * AST + cc] = areg[it];
        }
        #pragma unroll
        for (int it = 0; it < 4; it++) {
            int i = tid + it * 256;
            int r = i >> 4, cc = (i & 15) << 2;
            *(uint2*)&Bs2[r * AST + cc] = breg[it];
        }
    };

    float acc[2][4][4];
    #pragma unroll
    for (int mt = 0; mt < 2; mt++)
        #pragma unroll
        for (int nt = 0; nt < 4; nt++)
            #pragma unroll
            for (int i = 0; i < 4; i++) acc[mt][nt][i] = 0.f;

    const int NCH = K / 64;
    ldg_chunk(0);

    for (int ch = 0; ch < NCH; ch++) {
        __syncthreads();
        sts_chunk();
        __syncthreads();
        if (ch + 1 < NCH) ldg_chunk((ch + 1) * 64);

        #pragma unroll
        for (int ks = 0; ks < 4; ks++) {          // K=16 per step
            const int kb = ks * 16;
            uint32_t a[2][4], b[4][2];
            #pragma unroll
            for (int mt = 0; mt < 2; mt++) {
                int row = wm * 32 + mt * 16;
                a[mt][0] = *(const uint32_t*)&As2[(row + g) * AST + kb + 2 * tc];
                a[mt][1] = *(const uint32_t*)&As2[(row + 8 + g) * AST + kb + 2 * tc];
                a[mt][2] = *(const uint32_t*)&As2[(row + g) * AST + kb + 2 * tc + 8];
                a[mt][3] = *(const uint32_t*)&As2[(row + 8 + g) * AST + kb + 2 * tc + 8];
            }
            #pragma unroll
            for (int nt = 0; nt < 4; nt++) {
                int col = wn * 32 + nt * 8;
                b[nt][0] = *(const uint32_t*)&Bs2[(col + g) * AST + kb + 2 * tc];
                b[nt][1] = *(const uint32_t*)&Bs2[(col + g) * AST + kb + 2 * tc + 8];
            }
            #pragma unroll
            for (int mt = 0; mt < 2; mt++)
                #pragma unroll
                for (int nt = 0; nt < 4; nt++)
                    mma16(acc[mt][nt], a[mt], b[nt]);
        }
    }

    #pragma unroll
    for (int mt = 0; mt < 2; mt++) {
        #pragma unroll
        for (int nt = 0; nt < 4; nt++) {
            int lrow = wm * 32 + mt * 16 + g;
            int lcol = wn * 32 + nt * 8 + 2 * tc;
            float bx = biasb[lcol], by = biasb[lcol + 1];
            float2 v0 = { acc[mt][nt][0] + bx, acc[mt][nt][1] + by };
            float2 v1 = { acc[mt][nt][2] + bx, acc[mt][nt][3] + by };
            *(float2*)(Cb + (long)(cm0 + lrow) * ldc + cn0 + lcol) = v0;
            *(float2*)(Cb + (long)(cm0 + lrow + 8) * ldc + cn0 + lcol) = v1;
        }
    }
}

// ---------------------------------------------------------------------------
// Merged Q+K+V projection: 256 blocks (Q: 128, K-gather: 64, V-gather: 64).
// ---------------------------------------------------------------------------
__global__ __launch_bounds__(256, 2)
void qkv_mma(const float* __restrict__ q,  const float* __restrict__ Wq,
             const float* __restrict__ bq,
             const float* __restrict__ k,  const float* __restrict__ Wk,
             const float* __restrict__ bk,
             const float* __restrict__ v,  const float* __restrict__ Wv,
             const float* __restrict__ bv,
             float* __restrict__ Qp, float* __restrict__ Kg,
             float* __restrict__ Vg)
{
    __shared__ __align__(16) uint16_t As2[128 * AST];   // 18432 B
    __shared__ __align__(16) uint16_t Bs2[64 * AST];    //  9216 B

    const int b = blockIdx.x;
    const float *Ab, *Bb, *biasb;
    float* Cb;
    int rowMul, m0, cn0, ldc;

    if (b < 128) {
        int mt = b >> 4, nt = b & 15;
        Ab = q;  rowMul = 1;  m0 = mt * 128;
        cn0 = nt * 64;
        Bb = Wq + (long)cn0 * CD;  biasb = bq + cn0;
        Cb = Qp; ldc = CD;
    } else if (b < 192) {
        int idx = b - 128, h = idx >> 2, mt = idx & 3;
        Ab = k + (long)h * CD;  rowMul = 16;  m0 = mt * 128;
        cn0 = 0;
        Bb = Wk + (long)h * HD * CD;  biasb = bk + h * HD;
        Cb = Kg + (long)h * NKEY * HD; ldc = HD;
    } else {
        int idx = b - 192, h = idx >> 2, mt = idx & 3;
        Ab = v + (long)h * CD;  rowMul = 16;  m0 = mt * 128;
        cn0 = 0;
        Bb = Wv + (long)h * HD * CD;  biasb = bv + h * HD;
        Cb = Vg + (long)h * NKEY * HD; ldc = HD;
    }

    gemm_core(Ab, CD, rowMul, m0, Bb, CD, biasb, Cb, ldc, m0, cn0, CD, As2, Bs2);
}

// ---------------------------------------------------------------------------
// Output projection: out = AO @ Wo^T + bo
// ---------------------------------------------------------------------------
__global__ __launch_bounds__(256, 2)
void gemm_mma(const float* __restrict__ A,
              const float* __restrict__ B,
              const float* __restrict__ bias,
              float* __restrict__ C)
{
    __shared__ __align__(16) uint16_t As2[128 * AST];
    __shared__ __align__(16) uint16_t Bs2[64 * AST];
    const int m0 = blockIdx.y * 128;
    const int n0 = blockIdx.x * 64;
    gemm_core(A, CD, 1, m0, B + (long)n0 * CD, CD, bias + n0,
              C, CD, m0, n0, CD, As2, Bs2);
}

// ---------------------------------------------------------------------------
// Fused attention, split-K, fp16 mma (unchanged from R11): block = 32 queries
// x 1 head; 4 warps = 2 query-groups x 2 key-halves; flash merge at end.
// ---------------------------------------------------------------------------
__global__ __launch_bounds__(128)
void attn_mma(const float* __restrict__ Qp, const float* __restrict__ Kg,
              const float* __restrict__ Vg, float* __restrict__ AO)
{
    __shared__ __align__(16) uint16_t KVs2[2][64 * AST];   // 18432 B
    __shared__ __align__(16) uint16_t Ps2[2][32 * AST];    //  9216 B
    __shared__ float Osm[32 * 68];                         //  8704 B
    __shared__ float MS[32 * 2];                           //   256 B

    const int h    = blockIdx.y;
    const int q0   = blockIdx.x * 32;
    const int tid  = threadIdx.x;
    const int wid  = tid >> 5;
    const int lane = tid & 31;
    const int g    = lane >> 2;
    const int tc   = lane & 3;
    const int qg   = wid & 1;       // query group (rows qg*16 .. qg*16+15)
    const int half = wid >> 1;      // key half (0: keys 0..255, 1: 256..511)
    const int s    = tid & 63;      // staging index within half

    uint16_t* KVh = KVs2[half];
    uint16_t* Psh = Ps2[half];

    const float* Qb = Qp + (long)(q0 + qg * 16) * CD + h * HD;
    const float* Kb = Kg + (long)h * NKEY * HD + (long)half * 256 * HD;
    const float* Vb = Vg + (long)h * NKEY * HD + (long)half * 256 * HD;

    // Q fragments in registers: 4 k-steps of 16 over d=64
    uint32_t qa[4][4];
    #pragma unroll
    for (int ks = 0; ks < 4; ks++) {
        int kb = ks * 16;
        qa[ks][0] = pack2(Qb[(long)g * CD + kb + 2 * tc],
                          Qb[(long)g * CD + kb + 2 * tc + 1]);
        qa[ks][1] = pack2(Qb[(long)(g + 8) * CD + kb + 2 * tc],
                          Qb[(long)(g + 8) * CD + kb + 2 * tc + 1]);
        qa[ks][2] = pack2(Qb[(long)g * CD + kb + 2 * tc + 8],
                          Qb[(long)g * CD + kb + 2 * tc + 9]);
        qa[ks][3] = pack2(Qb[(long)(g + 8) * CD + kb + 2 * tc + 8],
                          Qb[(long)(g + 8) * CD + kb + 2 * tc + 9]);
    }

    float o[8][4];
    #pragma unroll
    for (int nt = 0; nt < 8; nt++)
        #pragma unroll
        for (int i = 0; i < 4; i++) o[nt][i] = 0.f;
    float m0_ = -1e30f, m1_ = -1e30f, s0 = 0.f, s1 = 0.f;

    for (int it = 0; it < 4; it++) {       // 4 chunks of 64 keys per half
        const int c0 = it * 64;
        __syncthreads();
        // Stage K chunk [key][d] as f16
        for (int i = s; i < 64 * 16; i += 64) {
            int r = i >> 4, cc = (i & 15) << 2;
            float4 t = *(const float4*)(Kb + (long)(c0 + r) * HD + cc);
            uint32_t* d = (uint32_t*)&KVh[r * AST + cc];
            d[0] = pack2(t.x, t.y);
            d[1] = pack2(t.z, t.w);
        }
        __syncthreads();

        // S = Q.K^T : 16q x 64key per warp, 4 k-steps of 16
        float sc[8][4];
        #pragma unroll
        for (int nt = 0; nt < 8; nt++)
            #pragma unroll
            for (int i = 0; i < 4; i++) sc[nt][i] = 0.f;
        #pragma unroll
        for (int ks = 0; ks < 4; ks++) {
            const int kb = ks * 16;
            #pragma unroll
            for (int nt = 0; nt < 8; nt++) {
                uint32_t b[2];
                b[0] = *(const uint32_t*)&KVh[(nt * 8 + g) * AST + kb + 2 * tc];
                b[1] = *(const uint32_t*)&KVh[(nt * 8 + g) * AST + kb + 2 * tc + 8];
                mma16(sc[nt], qa[ks], b);
            }
        }

        // Online softmax (rows r0 = qg*16+g -> c0/c1, r1 = r0+8 -> c2/c3)
        float mx0 = -1e30f, mx1 = -1e30f;
        #pragma unroll
        for (int nt = 0; nt < 8; nt++) {
            sc[nt][0] *= 0.125f; sc[nt][1] *= 0.125f;
            sc[nt][2] *= 0.125f; sc[nt][3] *= 0.125f;
            mx0 = fmaxf(mx0, fmaxf(sc[nt][0], sc[nt][1]));
            mx1 = fmaxf(mx1, fmaxf(sc[nt][2], sc[nt][3]));
        }
        mx0 = fmaxf(mx0, __shfl_xor_sync(0xffffffffu, mx0, 1));
        mx0 = fmaxf(mx0, __shfl_xor_sync(0xffffffffu, mx0, 2));
        mx1 = fmaxf(mx1, __shfl_xor_sync(0xffffffffu, mx1, 1));
        mx1 = fmaxf(mx1, __shfl_xor_sync(0xffffffffu, mx1, 2));
        float mn0 = fmaxf(m0_, mx0), mn1 = fmaxf(m1_, mx1);
        float f0 = __expf(m0_ - mn0), f1 = __expf(m1_ - mn1);
        m0_ = mn0; m1_ = mn1;
        float sum0 = 0.f, sum1 = 0.f;
        #pragma unroll
        for (int nt = 0; nt < 8; nt++) {
            sc[nt][0] = __expf(sc[nt][0] - mn0);
            sc[nt][1] = __expf(sc[nt][1] - mn0);
            sc[nt][2] = __expf(sc[nt][2] - mn1);
            sc[nt][3] = __expf(sc[nt][3] - mn1);
            sum0 += sc[nt][0] + sc[nt][1];
            sum1 += sc[nt][2] + sc[nt][3];
            int col = nt * 8 + 2 * tc;
            *(uint32_t*)&Psh[(qg * 16 + g) * AST + col]     = pack2(sc[nt][0], sc[nt][1]);
            *(uint32_t*)&Psh[(qg * 16 + 8 + g) * AST + col] = pack2(sc[nt][2], sc[nt][3]);
        }
        sum0 += __shfl_xor_sync(0xffffffffu, sum0, 1);
        sum0 += __shfl_xor_sync(0xffffffffu, sum0, 2);
        sum1 += __shfl_xor_sync(0xffffffffu, sum1, 1);
        sum1 += __shfl_xor_sync(0xffffffffu, sum1, 2);
        s0 = s0 * f0 + sum0;
        s1 = s1 * f1 + sum1;
        __syncthreads();

        // Stage V chunk TRANSPOSED [d][key] as f16
        for (int i = s; i < 64 * 16; i += 64) {
            int r = i >> 4, cc = (i & 15) << 2;    // r = key, cc = d
            float4 t = *(const float4*)(Vb + (long)(c0 + r) * HD + cc);
            KVh[(cc + 0) * AST + r] = __half_as_ushort(__float2half_rn(t.x));
            KVh[(cc + 1) * AST + r] = __half_as_ushort(__float2half_rn(t.y));
            KVh[(cc + 2) * AST + r] = __half_as_ushort(__float2half_rn(t.z));
            KVh[(cc + 3) * AST + r] = __half_as_ushort(__float2half_rn(t.w));
        }
        #pragma unroll
        for (int nt = 0; nt < 8; nt++) {
            o[nt][0] *= f0; o[nt][1] *= f0;
            o[nt][2] *= f1; o[nt][3] *= f1;
        }
        __syncthreads();

        // O += P.V : contraction over 64 keys (4 k-steps of 16), n = d
        #pragma unroll
        for (int ks = 0; ks < 4; ks++) {
            const int kb = ks * 16;
            uint32_t pa[4];
            pa[0] = *(const uint32_t*)&Psh[(qg * 16 + g) * AST + kb + 2 * tc];
            pa[1] = *(const uint32_t*)&Psh[(qg * 16 + 8 + g) * AST + kb + 2 * tc];
            pa[2] = *(const uint32_t*)&Psh[(qg * 16 + g) * AST + kb + 2 * tc + 8];
            pa[3] = *(const uint32_t*)&Psh[(qg * 16 + 8 + g) * AST + kb + 2 * tc + 8];
            #pragma unroll
            for (int nt = 0; nt < 8; nt++) {
                uint32_t b[2];
                b[0] = *(const uint32_t*)&KVh[(nt * 8 + g) * AST + kb + 2 * tc];
                b[1] = *(const uint32_t*)&KVh[(nt * 8 + g) * AST + kb + 2 * tc + 8];
                mma16(o[nt], pa, b);
            }
        }
    }

    // ---- Merge key-halves (flash-decode style) ----
    __syncthreads();
    const int row0 = qg * 16 + g;
    const int row1 = row0 + 8;

    if (half == 1) {
        if (tc == 0) {
            MS[row0 * 2] = m0_;  MS[row0 * 2 + 1] = s0;
            MS[row1 * 2] = m1_;  MS[row1 * 2 + 1] = s1;
        }
        #pragma unroll
        for (int nt = 0; nt < 8; nt++) {
            int col = nt * 8 + 2 * tc;
            Osm[row0 * 68 + col]     = o[nt][0];
            Osm[row0 * 68 + col + 1] = o[nt][1];
            Osm[row1 * 68 + col]     = o[nt][2];
            Osm[row1 * 68 + col + 1] = o[nt][3];
        }
    }
    __syncthreads();

    if (half == 0) {
        float mB0 = MS[row0 * 2], sB0 = MS[row0 * 2 + 1];
        float mB1 = MS[row1 * 2], sB1 = MS[row1 * 2 + 1];
        float mM0 = fmaxf(m0_, mB0), mM1 = fmaxf(m1_, mB1);
        float eA0 = __expf(m0_ - mM0), eB0 = __expf(mB0 - mM0);
        float eA1 = __expf(m1_ - mM1), eB1 = __expf(mB1 - mM1);
        float inv0 = 1.f / (s0 * eA0 + sB0 * eB0);
        float inv1 = 1.f / (s1 * eA1 + sB1 * eB1);
        #pragma unroll
        for (int nt = 0; nt < 8; nt++) {
            int col = nt * 8 + 2 * tc;
            float2 v0, v1;
            v0.x = (o[nt][0] * eA0 + Osm[row0 * 68 + col]     * eB0) * inv0;
            v0.y = (o[nt][1] * eA0 + Osm[row0 * 68 + col + 1] * eB0) * inv0;
            v1.x = (o[nt][2] * eA1 + Osm[row1 * 68 + col]     * eB1) * inv1;
            v1.y = (o[nt][3] * eA1 + Osm[row1 * 68 + col + 1] * eB1) * inv1;
            *(float2*)(AO + (long)(q0 + row0) * CD + h * HD + col) = v0;
            *(float2*)(AO + (long)(q0 + row1) * CD + h * HD + col) = v1;
        }
    }
}

// ---------------------------------------------------------------------------
// Launch
// ---------------------------------------------------------------------------
extern "C" void kernel_launch(void* const* d_in, const int* in_sizes, int n_in,
                              void* d_out, int out_size)
{
    (void)in_sizes; (void)n_in; (void)out_size;
    const float* q  = (const float*)d_in[0];
    const float* k  = (const float*)d_in[1];
    const float* v  = (const float*)d_in[2];
    const float* Wq = (const float*)d_in[3];
    const float* bq = (const float*)d_in[4];
    const float* Wk = (const float*)d_in[5];
    const float* bk = (const float*)d_in[6];
    const float* Wv = (const float*)d_in[7];
    const float* bv = (const float*)d_in[8];
    const float* Wo = (const float*)d_in[9];
    const float* bo = (const float*)d_in[10];
    float* out = (float*)d_out;

    float *Qp, *Kg, *Vg, *AO;
    cudaGetSymbolAddress((void**)&Qp, g_Qp);
    cudaGetSymbolAddress((void**)&Kg, g_Kg);
    cudaGetSymbolAddress((void**)&Vg, g_Vg);
    cudaGetSymbolAddress((void**)&AO, g_AO);

    // 1) Merged Q + K-gather + V-gather projections — 256 blocks, 2 CTA/SM
    qkv_mma<<<256, 256>>>(q, Wq, bq, k, Wk, bk, v, Wv, bv, Qp, Kg, Vg);

    // 2) Fused split-K attention — 512 blocks x 128 threads
    attn_mma<<<dim3(TQN / 32, NH), 128>>>(Qp, Kg, Vg, AO);

    // 3) Output projection — 128 blocks, 2 CTA/SM
    gemm_mma<<<dim3(CD / 64, TQN / 128), 256>>>(AO, Wo, bo, out);
}

// round 13
// speedup vs baseline: 1.0619x; 1.0619x over previous
#include <cuda_runtime.h>
#include <cuda_fp16.h>
#include <cstdint>

// Problem constants
#define CD    1024   // d_model
#define TQN   1024   // query tokens
#define NH    16     // heads
#define HD    64     // head dim
#define NKEY  512    // keys per head after HEPOS gather (8192/16)

#define AST   72     // smem row stride in halves (64 + 8 pad; conflict-free)

// ---------------------------------------------------------------------------
// Scratch (device globals) — intermediates stored as fp16 (bit-identical to
// the fp32-store + cvt-at-consumer scheme, since every consumer rounds to
// fp16 anyway).
// ---------------------------------------------------------------------------
__device__ __align__(256) __half g_Qp[TQN * CD];
__device__ __align__(256) __half g_Kg[NH * NKEY * HD];
__device__ __align__(256) __half g_Vg[NH * NKEY * HD];
__device__ __align__(256) __half g_AO[TQN * CD];

// ---------------------------------------------------------------------------
// fp16 mma.sync helpers
// ---------------------------------------------------------------------------
// pack2(lo, hi): f16x2 with lower half = lo
__device__ __forceinline__ uint32_t pack2(float lo, float hi) {
    uint32_t r;
    asm("cvt.rn.f16x2.f32 %0, %1, %2;" : "=r"(r) : "f"(hi), "f"(lo));
    return r;
}
__device__ __forceinline__ void mma16(float* c, const uint32_t* a, const uint32_t* b) {
    asm volatile(
        "mma.sync.aligned.m16n8k16.row.col.f32.f16.f16.f32 "
        "{%0,%1,%2,%3}, {%4,%5,%6,%7}, {%8,%9}, {%0,%1,%2,%3};\n"
        : "+f"(c[0]), "+f"(c[1]), "+f"(c[2]), "+f"(c[3])
        : "r"(a[0]), "r"(a[1]), "r"(a[2]), "r"(a[3]), "r"(b[0]), "r"(b[1]));
}

// ---------------------------------------------------------------------------
// QKV GEMM core: A fp32 (inputs), B fp32 (weights), C fp16 (intermediates).
// BM=128, BN=64, BK=64, 8 warps (4M x 2N), register-prefetch pipeline.
// ---------------------------------------------------------------------------
__device__ __forceinline__ void gemm_core_qkv(
    const float* __restrict__ Ab, int lda, int rowMul, int m0,
    const float* __restrict__ Bb, int ldb,
    const float* __restrict__ biasb,
    __half* __restrict__ Cb, int ldc, int cm0, int cn0, int K,
    uint16_t* As2, uint16_t* Bs2)
{
    const int tid  = threadIdx.x;
    const int wid  = tid >> 5;
    const int lane = tid & 31;
    const int g    = lane >> 2;
    const int tc   = lane & 3;
    const int wm   = wid & 3;
    const int wn   = wid >> 2;

    uint2 areg[8], breg[4];
    auto ldg_chunk = [&](int k0) {
        #pragma unroll
        for (int it = 0; it < 8; it++) {
            int i = tid + it * 256;
            int r = i >> 4, cc = (i & 15) << 2;
            float4 t = *(const float4*)(Ab + (long)(m0 + r) * rowMul * lda + k0 + cc);
            areg[it].x = pack2(t.x, t.y);
            areg[it].y = pack2(t.z, t.w);
        }
        #pragma unroll
        for (int it = 0; it < 4; it++) {
            int i = tid + it * 256;
            int r = i >> 4, cc = (i & 15) << 2;
            float4 t = *(const float4*)(Bb + (long)r * ldb + k0 + cc);
            breg[it].x = pack2(t.x, t.y);
            breg[it].y = pack2(t.z, t.w);
        }
    };
    auto sts_chunk = [&]() {
        #pragma unroll
        for (int it = 0; it < 8; it++) {
            int i = tid + it * 256;
            int r = i >> 4, cc = (i & 15) << 2;
            *(uint2*)&As2[r * AST + cc] = areg[it];
        }
        #pragma unroll
        for (int it = 0; it < 4; it++) {
            int i = tid + it * 256;
            int r = i >> 4, cc = (i & 15) << 2;
            *(uint2*)&Bs2[r * AST + cc] = breg[it];
        }
    };

    float acc[2][4][4];
    #pragma unroll
    for (int mt = 0; mt < 2; mt++)
        #pragma unroll
        for (int nt = 0; nt < 4; nt++)
            #pragma unroll
            for (int i = 0; i < 4; i++) acc[mt][nt][i] = 0.f;

    const int NCH = K / 64;
    ldg_chunk(0);

    for (int ch = 0; ch < NCH; ch++) {
        __syncthreads();
        sts_chunk();
        __syncthreads();
        if (ch + 1 < NCH) ldg_chunk((ch + 1) * 64);

        #pragma unroll
        for (int ks = 0; ks < 4; ks++) {
            const int kb = ks * 16;
            uint32_t a[2][4], b[4][2];
            #pragma unroll
            for (int mt = 0; mt < 2; mt++) {
                int row = wm * 32 + mt * 16;
                a[mt][0] = *(const uint32_t*)&As2[(row + g) * AST + kb + 2 * tc];
                a[mt][1] = *(const uint32_t*)&As2[(row + 8 + g) * AST + kb + 2 * tc];
                a[mt][2] = *(const uint32_t*)&As2[(row + g) * AST + kb + 2 * tc + 8];
                a[mt][3] = *(const uint32_t*)&As2[(row + 8 + g) * AST + kb + 2 * tc + 8];
            }
            #pragma unroll
            for (int nt = 0; nt < 4; nt++) {
                int col = wn * 32 + nt * 8;
                b[nt][0] = *(const uint32_t*)&Bs2[(col + g) * AST + kb + 2 * tc];
                b[nt][1] = *(const uint32_t*)&Bs2[(col + g) * AST + kb + 2 * tc + 8];
            }
            #pragma unroll
            for (int mt = 0; mt < 2; mt++)
                #pragma unroll
                for (int nt = 0; nt < 4; nt++)
                    mma16(acc[mt][nt], a[mt], b[nt]);
        }
    }

    // Epilogue: bias + pack to fp16 (one 32-bit store per 2 outputs)
    #pragma unroll
    for (int mt = 0; mt < 2; mt++) {
        #pragma unroll
        for (int nt = 0; nt < 4; nt++) {
            int lrow = wm * 32 + mt * 16 + g;
            int lcol = wn * 32 + nt * 8 + 2 * tc;
            float bx = biasb[lcol], by = biasb[lcol + 1];
            *(uint32_t*)&Cb[(long)(cm0 + lrow) * ldc + cn0 + lcol] =
                pack2(acc[mt][nt][0] + bx, acc[mt][nt][1] + by);
            *(uint32_t*)&Cb[(long)(cm0 + lrow + 8) * ldc + cn0 + lcol] =
                pack2(acc[mt][nt][2] + bx, acc[mt][nt][3] + by);
        }
    }
}

// ---------------------------------------------------------------------------
// Merged Q+K+V projection: 256 blocks (Q: 128, K-gather: 64, V-gather: 64).
// ---------------------------------------------------------------------------
__global__ __launch_bounds__(256, 2)
void qkv_mma(const float* __restrict__ q,  const float* __restrict__ Wq,
             const float* __restrict__ bq,
             const float* __restrict__ k,  const float* __restrict__ Wk,
             const float* __restrict__ bk,
             const float* __restrict__ v,  const float* __restrict__ Wv,
             const float* __restrict__ bv,
             __half* __restrict__ Qp, __half* __restrict__ Kg,
             __half* __restrict__ Vg)
{
    __shared__ __align__(16) uint16_t As2[128 * AST];
    __shared__ __align__(16) uint16_t Bs2[64 * AST];

    const int b = blockIdx.x;
    const float *Ab, *Bb, *biasb;
    __half* Cb;
    int rowMul, m0, cn0, ldc;

    if (b < 128) {
        int mt = b >> 4, nt = b & 15;
        Ab = q;  rowMul = 1;  m0 = mt * 128;
        cn0 = nt * 64;
        Bb = Wq + (long)cn0 * CD;  biasb = bq + cn0;
        Cb = Qp; ldc = CD;
    } else if (b < 192) {
        int idx = b - 128, h = idx >> 2, mt = idx & 3;
        Ab = k + (long)h * CD;  rowMul = 16;  m0 = mt * 128;
        cn0 = 0;
        Bb = Wk + (long)h * HD * CD;  biasb = bk + h * HD;
        Cb = Kg + (long)h * NKEY * HD; ldc = HD;
    } else {
        int idx = b - 192, h = idx >> 2, mt = idx & 3;
        Ab = v + (long)h * CD;  rowMul = 16;  m0 = mt * 128;
        cn0 = 0;
        Bb = Wv + (long)h * HD * CD;  biasb = bv + h * HD;
        Cb = Vg + (long)h * NKEY * HD; ldc = HD;
    }

    gemm_core_qkv(Ab, CD, rowMul, m0, Bb, CD, biasb, Cb, ldc, m0, cn0, CD, As2, Bs2);
}

// ---------------------------------------------------------------------------
// Output projection: out(fp32) = AO(fp16) @ Wo^T(fp32) + bo
// A staged as pure uint4 copies (no cvt); B packed at LDG as before.
// ---------------------------------------------------------------------------
__global__ __launch_bounds__(256, 2)
void gemm_mma(const __half* __restrict__ A,
              const float* __restrict__ B,
              const float* __restrict__ bias,
              float* __restrict__ C)
{
    __shared__ __align__(16) uint16_t As2[128 * AST];
    __shared__ __align__(16) uint16_t Bs2[64 * AST];

    const int tid  = threadIdx.x;
    const int wid  = tid >> 5;
    const int lane = tid & 31;
    const int g    = lane >> 2;
    const int tc   = lane & 3;
    const int wm   = wid & 3;
    const int wn   = wid >> 2;

    const int m0 = blockIdx.y * 128;
    const int n0 = blockIdx.x * 64;
    const __half* Ab = A + (long)m0 * CD;
    const float*  Bb = B + (long)n0 * CD;
    const float*  biasb = bias + n0;

    uint4 areg[4];
    uint2 breg[4];
    auto ldg_chunk = [&](int k0) {
        #pragma unroll
        for (int it = 0; it < 4; it++) {
            int i = tid + it * 256;
            int r = i >> 3, cc8 = (i & 7) << 3;
            areg[it] = *(const uint4*)(Ab + (long)r * CD + k0 + cc8);
        }
        #pragma unroll
        for (int it = 0; it < 4; it++) {
            int i = tid + it * 256;
            int r = i >> 4, cc = (i & 15) << 2;
            float4 t = *(const float4*)(Bb + (long)r * CD + k0 + cc);
            breg[it].x = pack2(t.x, t.y);
            breg[it].y = pack2(t.z, t.w);
        }
    };
    auto sts_chunk = [&]() {
        #pragma unroll
        for (int it = 0; it < 4; it++) {
            int i = tid + it * 256;
            int r = i >> 3, cc8 = (i & 7) << 3;
            *(uint4*)&As2[r * AST + cc8] = areg[it];
        }
        #pragma unroll
        for (int it = 0; it < 4; it++) {
            int i = tid + it * 256;
            int r = i >> 4, cc = (i & 15) << 2;
            *(uint2*)&Bs2[r * AST + cc] = breg[it];
        }
    };

    float acc[2][4][4];
    #pragma unroll
    for (int mt = 0; mt < 2; mt++)
        #pragma unroll
        for (int nt = 0; nt < 4; nt++)
            #pragma unroll
            for (int i = 0; i < 4; i++) acc[mt][nt][i] = 0.f;

    const int NCH = CD / 64;
    ldg_chunk(0);

    for (int ch = 0; ch < NCH; ch++) {
        __syncthreads();
        sts_chunk();
        __syncthreads();
        if (ch + 1 < NCH) ldg_chunk((ch + 1) * 64);

        #pragma unroll
        for (int ks = 0; ks < 4; ks++) {
            const int kb = ks * 16;
            uint32_t a[2][4], b[4][2];
            #pragma unroll
            for (int mt = 0; mt < 2; mt++) {
                int row = wm * 32 + mt * 16;
                a[mt][0] = *(const uint32_t*)&As2[(row + g) * AST + kb + 2 * tc];
                a[mt][1] = *(const uint32_t*)&As2[(row + 8 + g) * AST + kb + 2 * tc];
                a[mt][2] = *(const uint32_t*)&As2[(row + g) * AST + kb + 2 * tc + 8];
                a[mt][3] = *(const uint32_t*)&As2[(row + 8 + g) * AST + kb + 2 * tc + 8];
            }
            #pragma unroll
            for (int nt = 0; nt < 4; nt++) {
                int col = wn * 32 + nt * 8;
                b[nt][0] = *(const uint32_t*)&Bs2[(col + g) * AST + kb + 2 * tc];
                b[nt][1] = *(const uint32_t*)&Bs2[(col + g) * AST + kb + 2 * tc + 8];
            }
            #pragma unroll
            for (int mt = 0; mt < 2; mt++)
                #pragma unroll
                for (int nt = 0; nt < 4; nt++)
                    mma16(acc[mt][nt], a[mt], b[nt]);
        }
    }

    #pragma unroll
    for (int mt = 0; mt < 2; mt++) {
        #pragma unroll
        for (int nt = 0; nt < 4; nt++) {
            int lrow = wm * 32 + mt * 16 + g;
            int lcol = wn * 32 + nt * 8 + 2 * tc;
            float bx = biasb[lcol], by = biasb[lcol + 1];
            float2 v0 = { acc[mt][nt][0] + bx, acc[mt][nt][1] + by };
            float2 v1 = { acc[mt][nt][2] + bx, acc[mt][nt][3] + by };
            *(float2*)(C + (long)(m0 + lrow) * CD + n0 + lcol) = v0;
            *(float2*)(C + (long)(m0 + lrow + 8) * CD + n0 + lcol) = v1;
        }
    }
}

// ---------------------------------------------------------------------------
// Fused attention, split-K, fp16 in/out: block = 32 queries x 1 head; 4 warps
// = 2 query-groups x 2 key-halves. K staged via uint4 copy; V prefetched into
// registers during the S-phase mma (hides LDG), then transposed into smem.
// ---------------------------------------------------------------------------
__global__ __launch_bounds__(128, 3)
void attn_mma(const __half* __restrict__ Qp, const __half* __restrict__ Kg,
              const __half* __restrict__ Vg, __half* __restrict__ AO)
{
    __shared__ __align__(16) uint16_t KVs2[2][64 * AST];
    __shared__ __align__(16) uint16_t Ps2[2][32 * AST];
    __shared__ float Osm[32 * 68];
    __shared__ float MS[32 * 2];

    const int h    = blockIdx.y;
    const int q0   = blockIdx.x * 32;
    const int tid  = threadIdx.x;
    const int wid  = tid >> 5;
    const int lane = tid & 31;
    const int g    = lane >> 2;
    const int tc   = lane & 3;
    const int qg   = wid & 1;
    const int half = wid >> 1;
    const int s    = tid & 63;

    uint16_t* KVh = KVs2[half];
    uint16_t* Psh = Ps2[half];

    const __half* Qb = Qp + (long)(q0 + qg * 16) * CD + h * HD;
    const __half* Kb = Kg + (long)h * NKEY * HD + (long)half * 256 * HD;
    const __half* Vb = Vg + (long)h * NKEY * HD + (long)half * 256 * HD;

    // Q fragments: direct 32-bit loads (fp16 storage)
    uint32_t qa[4][4];
    #pragma unroll
    for (int ks = 0; ks < 4; ks++) {
        int kb = ks * 16;
        qa[ks][0] = *(const uint32_t*)&Qb[(long)g * CD + kb + 2 * tc];
        qa[ks][1] = *(const uint32_t*)&Qb[(long)(g + 8) * CD + kb + 2 * tc];
        qa[ks][2] = *(const uint32_t*)&Qb[(long)g * CD + kb + 2 * tc + 8];
        qa[ks][3] = *(const uint32_t*)&Qb[(long)(g + 8) * CD + kb + 2 * tc + 8];
    }

    float o[8][4];
    #pragma unroll
    for (int nt = 0; nt < 8; nt++)
        #pragma unroll
        for (int i = 0; i < 4; i++) o[nt][i] = 0.f;
    float m0_ = -1e30f, m1_ = -1e30f, s0 = 0.f, s1 = 0.f;

    uint4 vreg[8];   // V-chunk prefetch: 8 x (8 halves) per thread

    for (int it = 0; it < 4; it++) {       // 4 chunks of 64 keys per half
        const int c0 = it * 64;
        __syncthreads();
        // Stage K chunk [key][d]: pure uint4 copies (8 per thread)
        #pragma unroll
        for (int it2 = 0; it2 < 8; it2++) {
            int i = s + it2 * 64;
            int r = i >> 3, cc8 = (i & 7) << 3;
            *(uint4*)&KVh[r * AST + cc8] = *(const uint4*)(Kb + (long)(c0 + r) * HD + cc8);
        }
        // Prefetch V chunk into registers (lands during S-phase mma)
        #pragma unroll
        for (int it2 = 0; it2 < 8; it2++) {
            int i = s + it2 * 64;
            int r = i >> 3, cc8 = (i & 7) << 3;
            vreg[it2] = *(const uint4*)(Vb + (long)(c0 + r) * HD + cc8);
        }
        __syncthreads();

        // S = Q.K^T : 16q x 64key per warp, 4 k-steps of 16
        float sc[8][4];
        #pragma unroll
        for (int nt = 0; nt < 8; nt++)
            #pragma unroll
            for (int i = 0; i < 4; i++) sc[nt][i] = 0.f;
        #pragma unroll
        for (int ks = 0; ks < 4; ks++) {
            const int kb = ks * 16;
            #pragma unroll
            for (int nt = 0; nt < 8; nt++) {
                uint32_t b[2];
                b[0] = *(const uint32_t*)&KVh[(nt * 8 + g) * AST + kb + 2 * tc];
                b[1] = *(const uint32_t*)&KVh[(nt * 8 + g) * AST + kb + 2 * tc + 8];
                mma16(sc[nt], qa[ks], b);
            }
        }

        // Online softmax
        float mx0 = -1e30f, mx1 = -1e30f;
        #pragma unroll
        for (int nt = 0; nt < 8; nt++) {
            sc[nt][0] *= 0.125f; sc[nt][1] *= 0.125f;
            sc[nt][2] *= 0.125f; sc[nt][3] *= 0.125f;
            mx0 = fmaxf(mx0, fmaxf(sc[nt][0], sc[nt][1]));
            mx1 = fmaxf(mx1, fmaxf(sc[nt][2], sc[nt][3]));
        }
        mx0 = fmaxf(mx0, __shfl_xor_sync(0xffffffffu, mx0, 1));
        mx0 = fmaxf(mx0, __shfl_xor_sync(0xffffffffu, mx0, 2));
        mx1 = fmaxf(mx1, __shfl_xor_sync(0xffffffffu, mx1, 1));
        mx1 = fmaxf(mx1, __shfl_xor_sync(0xffffffffu, mx1, 2));
        float mn0 = fmaxf(m0_, mx0), mn1 = fmaxf(m1_, mx1);
        float f0 = __expf(m0_ - mn0), f1 = __expf(m1_ - mn1);
        m0_ = mn0; m1_ = mn1;
        float sum0 = 0.f, sum1 = 0.f;
        #pragma unroll
        for (int nt = 0; nt < 8; nt++) {
            sc[nt][0] = __expf(sc[nt][0] - mn0);
            sc[nt][1] = __expf(sc[nt][1] - mn0);
            sc[nt][2] = __expf(sc[nt][2] - mn1);
            sc[nt][3] = __expf(sc[nt][3] - mn1);
            sum0 += sc[nt][0] + sc[nt][1];
            sum1 += sc[nt][2] + sc[nt][3];
            int col = nt * 8 + 2 * tc;
            *(uint32_t*)&Psh[(qg * 16 + g) * AST + col]     = pack2(sc[nt][0], sc[nt][1]);
            *(uint32_t*)&Psh[(qg * 16 + 8 + g) * AST + col] = pack2(sc[nt][2], sc[nt][3]);
        }
        sum0 += __shfl_xor_sync(0xffffffffu, sum0, 1);
        sum0 += __shfl_xor_sync(0xffffffffu, sum0, 2);
        sum1 += __shfl_xor_sync(0xffffffffu, sum1, 1);
        sum1 += __shfl_xor_sync(0xffffffffu, sum1, 2);
        s0 = s0 * f0 + sum0;
        s1 = s1 * f1 + sum1;
        __syncthreads();

        // Stage V^T [d][key] from prefetch registers
        #pragma unroll
        for (int it2 = 0; it2 < 8; it2++) {
            int i = s + it2 * 64;
            int r = i >> 3, cc8 = (i & 7) << 3;     // r = key, cc8 = d base
            const uint16_t* hsrc = (const uint16_t*)&vreg[it2];
            #pragma unroll
            for (int j = 0; j < 8; j++)
                KVh[(cc8 + j) * AST + r] = hsrc[j];
        }
        #pragma unroll
        for (int nt = 0; nt < 8; nt++) {
            o[nt][0] *= f0; o[nt][1] *= f0;
            o[nt][2] *= f1; o[nt][3] *= f1;
        }
        __syncthreads();

        // O += P.V
        #pragma unroll
        for (int ks = 0; ks < 4; ks++) {
            const int kb = ks * 16;
            uint32_t pa[4];
            pa[0] = *(const uint32_t*)&Psh[(qg * 16 + g) * AST + kb + 2 * tc];
            pa[1] = *(const uint32_t*)&Psh[(qg * 16 + 8 + g) * AST + kb + 2 * tc];
            pa[2] = *(const uint32_t*)&Psh[(qg * 16 + g) * AST + kb + 2 * tc + 8];
            pa[3] = *(const uint32_t*)&Psh[(qg * 16 + 8 + g) * AST + kb + 2 * tc + 8];
            #pragma unroll
            for (int nt = 0; nt < 8; nt++) {
                uint32_t b[2];
                b[0] = *(const uint32_t*)&KVh[(nt * 8 + g) * AST + kb + 2 * tc];
                b[1] = *(const uint32_t*)&KVh[(nt * 8 + g) * AST + kb + 2 * tc + 8];
                mma16(o[nt], pa, b);
            }
        }
    }

    // ---- Merge key-halves ----
    __syncthreads();
    const int row0 = qg * 16 + g;
    const int row1 = row0 + 8;

    if (half == 1) {
        if (tc == 0) {
            MS[row0 * 2] = m0_;  MS[row0 * 2 + 1] = s0;
            MS[row1 * 2] = m1_;  MS[row1 * 2 + 1] = s1;
        }
        #pragma unroll
        for (int nt = 0; nt < 8; nt++) {
            int col = nt * 8 + 2 * tc;
            Osm[row0 * 68 + col]     = o[nt][0];
            Osm[row0 * 68 + col + 1] = o[nt][1];
            Osm[row1 * 68 + col]     = o[nt][2];
            Osm[row1 * 68 + col + 1] = o[nt][3];
        }
    }
    __syncthreads();

    if (half == 0) {
        float mB0 = MS[row0 * 2], sB0 = MS[row0 * 2 + 1];
        float mB1 = MS[row1 * 2], sB1 = MS[row1 * 2 + 1];
        float mM0 = fmaxf(m0_, mB0), mM1 = fmaxf(m1_, mB1);
        float eA0 = __expf(m0_ - mM0), eB0 = __expf(mB0 - mM0);
        float eA1 = __expf(m1_ - mM1), eB1 = __expf(mB1 - mM1);
        float inv0 = 1.f / (s0 * eA0 + sB0 * eB0);
        float inv1 = 1.f / (s1 * eA1 + sB1 * eB1);
        #pragma unroll
        for (int nt = 0; nt < 8; nt++) {
            int col = nt * 8 + 2 * tc;
            float ax = (o[nt][0] * eA0 + Osm[row0 * 68 + col]     * eB0) * inv0;
            float ay = (o[nt][1] * eA0 + Osm[row0 * 68 + col + 1] * eB0) * inv0;
            float bx = (o[nt][2] * eA1 + Osm[row1 * 68 + col]     * eB1) * inv1;
            float by = (o[nt][3] * eA1 + Osm[row1 * 68 + col + 1] * eB1) * inv1;
            *(uint32_t*)&AO[(long)(q0 + row0) * CD + h * HD + col] = pack2(ax, ay);
            *(uint32_t*)&AO[(long)(q0 + row1) * CD + h * HD + col] = pack2(bx, by);
        }
    }
}

// ---------------------------------------------------------------------------
// Launch
// ---------------------------------------------------------------------------
extern "C" void kernel_launch(void* const* d_in, const int* in_sizes, int n_in,
                              void* d_out, int out_size)
{
    (void)in_sizes; (void)n_in; (void)out_size;
    const float* q  = (const float*)d_in[0];
    const float* k  = (const float*)d_in[1];
    const float* v  = (const float*)d_in[2];
    const float* Wq = (const float*)d_in[3];
    const float* bq = (const float*)d_in[4];
    const float* Wk = (const float*)d_in[5];
    const float* bk = (const float*)d_in[6];
    const float* Wv = (const float*)d_in[7];
    const float* bv = (const float*)d_in[8];
    const float* Wo = (const float*)d_in[9];
    const float* bo = (const float*)d_in[10];
    float* out = (float*)d_out;

    __half *Qp, *Kg, *Vg, *AO;
    cudaGetSymbolAddress((void**)&Qp, g_Qp);
    cudaGetSymbolAddress((void**)&Kg, g_Kg);
    cudaGetSymbolAddress((void**)&Vg, g_Vg);
    cudaGetSymbolAddress((void**)&AO, g_AO);

    // 1) Merged Q + K-gather + V-gather projections — 256 blocks
    qkv_mma<<<256, 256>>>(q, Wq, bq, k, Wk, bk, v, Wv, bv, Qp, Kg, Vg);

    // 2) Fused split-K attention — 512 blocks x 128 threads
    attn_mma<<<dim3(TQN / 32, NH), 128>>>(Qp, Kg, Vg, AO);

    // 3) Output projection — 128 blocks
    gemm_mma<<<dim3(CD / 64, TQN / 128), 256>>>(AO, Wo, bo, out);
}